// round 2
// baseline (speedup 1.0000x reference)
#include <cuda_runtime.h>
#include <math.h>

#define FULL 0xFFFFFFFFu

constexpr int Hh   = 16;   // heads
constexpr int Ee   = 64;   // head dim
constexpr int TQ   = 16;   // queries per block (one per warp)
constexpr int TS   = 64;   // keys per smem tile
constexpr int KPAD = 68;   // padded floats per key row (17 x 16B -> conflict-free LDS.128)

__device__ __forceinline__ void warp_argmin(float v, int lane, float& mv, int& ml) {
    mv = v; ml = lane;
    #pragma unroll
    for (int off = 16; off; off >>= 1) {
        float ov = __shfl_xor_sync(FULL, mv, off);
        int   ol = __shfl_xor_sync(FULL, ml, off);
        if (ov < mv || (ov == mv && ol < ml)) { mv = ov; ml = ol; }
    }
}

__global__ __launch_bounds__(512, 1)
void topk_attn_kernel(const float* __restrict__ Q,
                      const float* __restrict__ K,
                      const float* __restrict__ V,
                      float* __restrict__ O,
                      int T, int S)
{
    __shared__ float ktile[TS * KPAD];

    const int h    = blockIdx.y;
    const int warp = threadIdx.x >> 5;
    const int lane = threadIdx.x & 31;
    const int t    = blockIdx.x * TQ + warp;

    // ---- load this warp's query row into registers, pre-scaled by 1/sqrt(E) ----
    float4 qv[Ee / 4];
    {
        const float4* qrow = reinterpret_cast<const float4*>(Q + ((size_t)t * Hh + h) * Ee);
        #pragma unroll
        for (int j = 0; j < Ee / 4; j++) {
            float4 v = qrow[j];
            qv[j] = make_float4(v.x * 0.125f, v.y * 0.125f, v.z * 0.125f, v.w * 0.125f);
        }
    }

    // running top-32: each lane owns one (value, key-index) slot
    float topv = -INFINITY;
    int   topi = 0;

    const int ntiles = S / TS;
    const int rowF4  = (Hh * Ee) / 4;  // float4 stride between consecutive keys in gmem

    for (int tile = 0; tile < ntiles; tile++) {
        // ---- cooperative, coalesced load of TS keys into padded smem ----
        {
            const float4* ksrc =
                reinterpret_cast<const float4*>(K + (((size_t)tile * TS) * Hh + h) * Ee);
            #pragma unroll
            for (int r = 0; r < (TS * Ee / 4) / 512; r++) {
                int idx = r * 512 + threadIdx.x;
                int s   = idx >> 4;   // 16 float4 per key row
                int e4  = idx & 15;
                float4 v = ksrc[(size_t)s * rowF4 + e4];
                *reinterpret_cast<float4*>(&ktile[s * KPAD + e4 * 4]) = v;
            }
        }
        __syncthreads();

        // ---- each lane: one full dot per chunk of 32 keys ----
        #pragma unroll
        for (int c = 0; c < TS / 32; c++) {
            const int sl = c * 32 + lane;
            const float4* krow = reinterpret_cast<const float4*>(&ktile[sl * KPAD]);
            float acc = 0.f;
            #pragma unroll
            for (int j = 0; j < Ee / 4; j++) {
                float4 kv = krow[j];
                acc += qv[j].x * kv.x;
                acc += qv[j].y * kv.y;
                acc += qv[j].z * kv.z;
                acc += qv[j].w * kv.w;
            }
            const int sg = tile * TS + sl;

            // ---- warp-collective top-32 insert ----
            float mv; int ml;
            warp_argmin(topv, lane, mv, ml);
            unsigned m = __ballot_sync(FULL, acc > mv);
            while (m) {
                int src = __ffs(m) - 1;
                m &= m - 1;
                float v  = __shfl_sync(FULL, acc, src);
                int   vi = __shfl_sync(FULL, sg,  src);
                if (v > mv) {                       // uniform (mv uniform after reduce)
                    if (lane == ml) { topv = v; topi = vi; }
                    warp_argmin(topv, lane, mv, ml);
                }
            }
        }
        __syncthreads();
    }

    // ---- softmax over the 32 kept scores (one per lane) ----
    float mx = topv;
    #pragma unroll
    for (int o = 16; o; o >>= 1) mx = fmaxf(mx, __shfl_xor_sync(FULL, mx, o));
    float p  = __expf(topv - mx);
    float ps = p;
    #pragma unroll
    for (int o = 16; o; o >>= 1) ps += __shfl_xor_sync(FULL, ps, o);
    const float w = p / ps;

    // ---- gather 32 V rows, weighted sum; lane handles output elems 2*lane, 2*lane+1 ----
    float2 acc2 = make_float2(0.f, 0.f);
    #pragma unroll 1
    for (int j = 0; j < 32; j++) {
        float wj = __shfl_sync(FULL, w,    j);
        int   ij = __shfl_sync(FULL, topi, j);
        const float2* vrow =
            reinterpret_cast<const float2*>(V + ((size_t)ij * Hh + h) * Ee);
        float2 vv = vrow[lane];
        acc2.x += wj * vv.x;
        acc2.y += wj * vv.y;
    }
    float2* orow = reinterpret_cast<float2*>(O + ((size_t)t * Hh + h) * Ee);
    orow[lane] = acc2;
}

extern "C" void kernel_launch(void* const* d_in, const int* in_sizes, int n_in,
                              void* d_out, int out_size)
{
    const float* Q = (const float*)d_in[0];
    const float* K = (const float*)d_in[1];
    const float* V = (const float*)d_in[2];
    float*       O = (float*)d_out;

    const int T = in_sizes[0] / (Hh * Ee);
    const int S = in_sizes[1] / (Hh * Ee);

    dim3 grid(T / TQ, Hh);
    topk_attn_kernel<<<grid, 512>>>(Q, K, V, O, T, S);
}

// round 3
// speedup vs baseline: 2.4032x; 2.4032x over previous
#include <cuda_runtime.h>
#include <math.h>
#include <stdint.h>

#define FULL 0xFFFFFFFFu

constexpr int Hh   = 16;        // heads
constexpr int Ee   = 64;        // head dim
constexpr int TQ   = 16;        // queries per block (one warp per query for selection)
constexpr int KT   = 512;       // keys per smem tile (16 warps x 32 keys)
constexpr int KPAD = 68;        // padded floats per key row -> conflict-free LDS.128
constexpr int SPAD = 516;       // padded floats per score row

// monotone float -> uint map (order preserving)
__device__ __forceinline__ unsigned fmap(float f) {
    unsigned u = __float_as_uint(f);
    return (u & 0x80000000u) ? ~u : (u | 0x80000000u);
}
__device__ __forceinline__ float funmap(unsigned u) {
    return (u & 0x80000000u) ? __uint_as_float(u ^ 0x80000000u)
                             : __uint_as_float(~u);
}

__global__ void __launch_bounds__(512, 1)
topk_attn_kernel(const float* __restrict__ Q,
                 const float* __restrict__ K,
                 const float* __restrict__ V,
                 float* __restrict__ O,
                 int T, int S)
{
    extern __shared__ float sm[];
    float* ktile  = sm;                       // KT * KPAD
    float* scores = sm + KT * KPAD;           // TQ * SPAD
    float* qs     = scores + TQ * SPAD;       // TQ * Ee

    const int h     = blockIdx.y;
    const int tid   = threadIdx.x;
    const int warp  = tid >> 5;
    const int lane  = tid & 31;
    const int tbase = blockIdx.x * TQ;

    // ---- stage 16 query rows into smem, pre-scaled by 1/sqrt(E)=0.125 ----
    if (tid < 256) {
        int q  = tid >> 4;
        int e4 = tid & 15;
        float4 v = *reinterpret_cast<const float4*>(
            Q + ((size_t)(tbase + q) * Hh + h) * Ee + e4 * 4);
        v.x *= 0.125f; v.y *= 0.125f; v.z *= 0.125f; v.w *= 0.125f;
        *reinterpret_cast<float4*>(&qs[q * Ee + e4 * 4]) = v;
    }

    // ---- per-warp (query = warp) top-32 state: one slot per lane ----
    unsigned topu = 0u;   // mapped score (0 < any real mapped score)
    int      topi = 0;
    unsigned mvu  = 0u;   // cached min of top set (warp-uniform)
    int      ml   = 0;    // lane holding the min (warp-uniform)

    const int rowF4 = (Hh * Ee) / 4;
    const unsigned ka_base = (unsigned)__cvta_generic_to_shared(
        &ktile[(warp * 32 + lane) * KPAD]);
    const unsigned qa_base = (unsigned)__cvta_generic_to_shared(qs);

    const int ntiles = S / KT;
    #pragma unroll 1
    for (int tile = 0; tile < ntiles; tile++) {
        // ---- P1: cooperative coalesced stage of KT key rows into padded smem ----
        {
            const float4* ksrc = reinterpret_cast<const float4*>(
                K + (((size_t)tile * KT) * Hh + h) * Ee);
            #pragma unroll
            for (int r = 0; r < (KT * Ee / 4) / 512; r++) {
                int idx = r * 512 + tid;
                int s   = idx >> 4;
                int e4  = idx & 15;
                float4 v = ksrc[(size_t)s * rowF4 + e4];
                *reinterpret_cast<float4*>(&ktile[s * KPAD + e4 * 4]) = v;
            }
        }
        __syncthreads();

        // ---- P2: lane = key (warp*32+lane); compute scores vs all 16 queries ----
        {
            unsigned long long acc[TQ];
            #pragma unroll
            for (int q = 0; q < TQ; q++) acc[q] = 0ull;   // (0.f, 0.f)

            #pragma unroll
            for (int e4 = 0; e4 < Ee / 4; e4++) {
                unsigned long long k0, k1;
                asm volatile("ld.shared.v2.u64 {%0,%1},[%2];"
                             : "=l"(k0), "=l"(k1) : "r"(ka_base + e4 * 16));
                #pragma unroll
                for (int q = 0; q < TQ; q++) {
                    unsigned long long q0, q1;
                    asm volatile("ld.shared.v2.u64 {%0,%1},[%2];"
                                 : "=l"(q0), "=l"(q1)
                                 : "r"(qa_base + q * (Ee * 4) + e4 * 16));
                    asm volatile("fma.rn.f32x2 %0, %1, %2, %0;"
                                 : "+l"(acc[q]) : "l"(k0), "l"(q0));
                    asm volatile("fma.rn.f32x2 %0, %1, %2, %0;"
                                 : "+l"(acc[q]) : "l"(k1), "l"(q1));
                }
            }
            // horizontal (even+odd e) and write to score matrix
            #pragma unroll
            for (int q = 0; q < TQ; q++) {
                float lo = __uint_as_float((unsigned)(acc[q] & 0xffffffffull));
                float hi = __uint_as_float((unsigned)(acc[q] >> 32));
                scores[q * SPAD + warp * 32 + lane] = lo + hi;
            }
        }
        __syncthreads();

        // ---- P3: selection — warp w scans query w's KT fresh scores ----
        {
            const float* srow = scores + warp * SPAD;
            const int kb = tile * KT;
            #pragma unroll 1
            for (int r = 0; r < KT / 32; r++) {
                float sc   = srow[r * 32 + lane];
                unsigned c = fmap(sc);
                int idx    = kb + r * 32 + lane;
                unsigned m = __ballot_sync(FULL, c > mvu);
                while (m) {
                    int src = __ffs(m) - 1;
                    m &= m - 1;
                    unsigned v  = __shfl_sync(FULL, c,   src);
                    int      vi = __shfl_sync(FULL, idx, src);
                    if (v > mvu) {                 // warp-uniform
                        if (lane == ml) { topu = v; topi = vi; }
                        unsigned mn;
                        asm("redux.sync.min.u32 %0, %1, 0xffffffff;"
                            : "=r"(mn) : "r"(topu));
                        mvu = mn;
                        unsigned b = __ballot_sync(FULL, topu == mn);
                        ml = __ffs(b) - 1;
                    }
                }
            }
        }
        // next-iteration P1 sync orders P3 reads vs P2 score overwrites
    }

    // ---- softmax over the 32 kept scores (one per lane) ----
    float sv = funmap(topu);
    float mx = sv;
    #pragma unroll
    for (int o = 16; o; o >>= 1) mx = fmaxf(mx, __shfl_xor_sync(FULL, mx, o));
    float p  = __expf(sv - mx);
    float ps = p;
    #pragma unroll
    for (int o = 16; o; o >>= 1) ps += __shfl_xor_sync(FULL, ps, o);
    const float w = p / ps;

    // ---- gather 32 V rows, weighted sum; lane covers elems 2*lane, 2*lane+1 ----
    float2 acc2 = make_float2(0.f, 0.f);
    #pragma unroll 1
    for (int j = 0; j < 32; j++) {
        float wj = __shfl_sync(FULL, w,    j);
        int   ij = __shfl_sync(FULL, topi, j);
        const float2* vrow =
            reinterpret_cast<const float2*>(V + ((size_t)ij * Hh + h) * Ee);
        float2 vv = vrow[lane];
        acc2.x += wj * vv.x;
        acc2.y += wj * vv.y;
    }
    const int t = tbase + warp;
    float2* orow = reinterpret_cast<float2*>(O + ((size_t)t * Hh + h) * Ee);
    orow[lane] = acc2;
}

extern "C" void kernel_launch(void* const* d_in, const int* in_sizes, int n_in,
                              void* d_out, int out_size)
{
    const float* Q = (const float*)d_in[0];
    const float* K = (const float*)d_in[1];
    const float* V = (const float*)d_in[2];
    float*       O = (float*)d_out;

    const int T = in_sizes[0] / (Hh * Ee);
    const int S = in_sizes[1] / (Hh * Ee);

    const int smem_bytes = (KT * KPAD + TQ * SPAD + TQ * Ee) * (int)sizeof(float);
    cudaFuncSetAttribute(topk_attn_kernel,
                         cudaFuncAttributeMaxDynamicSharedMemorySize, smem_bytes);

    dim3 grid(T / TQ, Hh);
    topk_attn_kernel<<<grid, 512, smem_bytes>>>(Q, K, V, O, T, S);
}